// round 15
// baseline (speedup 1.0000x reference)
#include <cuda_runtime.h>
#include <cuda_bf16.h>
#include <cstdint>

// Problem constants
#define T_DIM 2048
#define B_DIM 2
#define E_DIM 1024
#define H_DIM 16
#define DH    64
#define TB    (T_DIM * B_DIM)   // 4096
#define E3    (3 * E_DIM)       // 3072

// ---------------------------------------------------------------------------
// Device scratch (no runtime allocation allowed)
// ---------------------------------------------------------------------------
__device__ __nv_bfloat16 g_Qh[B_DIM * H_DIM * T_DIM * DH], g_Ql[B_DIM * H_DIM * T_DIM * DH];
__device__ __nv_bfloat16 g_Kh[B_DIM * H_DIM * T_DIM * DH], g_Kl[B_DIM * H_DIM * T_DIM * DH];
// V stored TRANSPOSED: [bh][d][t]
__device__ __nv_bfloat16 g_Vth[B_DIM * H_DIM * DH * T_DIM], g_Vtl[B_DIM * H_DIM * DH * T_DIM];

__device__ __nv_bfloat16 g_Xhi[TB * E_DIM],  g_Xlo[TB * E_DIM];        // query split
__device__ __nv_bfloat16 g_Whi[E3 * E_DIM],  g_Wlo[E3 * E_DIM];        // in_proj_weight split
__device__ __nv_bfloat16 g_OWhi[E_DIM * E_DIM], g_OWlo[E_DIM * E_DIM]; // out_w split
__device__ __nv_bfloat16 g_Ahi[TB * E_DIM],  g_Alo[TB * E_DIM];        // attn output split

// ---------------------------------------------------------------------------
// Helpers (proven)
// ---------------------------------------------------------------------------
__device__ __forceinline__ uint32_t smem_u32(const void* p) {
    uint32_t a;
    asm("{ .reg .u64 t; cvta.to.shared.u64 t, %1; cvt.u32.u64 %0, t; }" : "=r"(a) : "l"(p));
    return a;
}

__device__ __forceinline__ void ldsm_x4(uint32_t& r0, uint32_t& r1, uint32_t& r2,
                                        uint32_t& r3, uint32_t addr) {
    asm volatile("ldmatrix.sync.aligned.m8n8.x4.shared.b16 {%0,%1,%2,%3}, [%4];"
                 : "=r"(r0), "=r"(r1), "=r"(r2), "=r"(r3) : "r"(addr));
}

__device__ __forceinline__ void mma_bf16(float* d, const uint32_t* a, const uint32_t* b) {
    asm volatile(
        "mma.sync.aligned.m16n8k16.row.col.f32.bf16.bf16.f32 "
        "{%0,%1,%2,%3}, {%4,%5,%6,%7}, {%8,%9}, {%0,%1,%2,%3};"
        : "+f"(d[0]), "+f"(d[1]), "+f"(d[2]), "+f"(d[3])
        : "r"(a[0]), "r"(a[1]), "r"(a[2]), "r"(a[3]), "r"(b[0]), "r"(b[1]));
}

__device__ __forceinline__ uint32_t pack2(float a, float b) {
    __nv_bfloat162 p(__float2bfloat16(a), __float2bfloat16(b));
    return *reinterpret_cast<uint32_t*>(&p);
}
__device__ __forceinline__ uint32_t pack_hi2(float a, float b, float& ra, float& rb) {
    __nv_bfloat16 ha = __float2bfloat16(a), hb = __float2bfloat16(b);
    ra = a - __bfloat162float(ha);
    rb = b - __bfloat162float(hb);
    __nv_bfloat162 p(ha, hb);
    return *reinterpret_cast<uint32_t*>(&p);
}

// ---------------------------------------------------------------------------
// Kernel 0: fp32 -> (bf16 hi, bf16 lo) split conversion (proven)
// ---------------------------------------------------------------------------
__global__ __launch_bounds__(256) void cvt_split_kernel(
    const float* __restrict__ x, __nv_bfloat16* __restrict__ hi,
    __nv_bfloat16* __restrict__ lo, int n4)
{
    int i = blockIdx.x * blockDim.x + threadIdx.x;
    if (i >= n4) return;
    float4 v = reinterpret_cast<const float4*>(x)[i];
    __nv_bfloat16 h0 = __float2bfloat16(v.x), h1 = __float2bfloat16(v.y);
    __nv_bfloat16 h2 = __float2bfloat16(v.z), h3 = __float2bfloat16(v.w);
    __nv_bfloat16 l0 = __float2bfloat16(v.x - __bfloat162float(h0));
    __nv_bfloat16 l1 = __float2bfloat16(v.y - __bfloat162float(h1));
    __nv_bfloat16 l2 = __float2bfloat16(v.z - __bfloat162float(h2));
    __nv_bfloat16 l3 = __float2bfloat16(v.w - __bfloat162float(h3));
    __nv_bfloat162* hp = reinterpret_cast<__nv_bfloat162*>(hi);
    __nv_bfloat162* lp = reinterpret_cast<__nv_bfloat162*>(lo);
    hp[2 * i + 0] = __nv_bfloat162(h0, h1);
    hp[2 * i + 1] = __nv_bfloat162(h2, h3);
    lp[2 * i + 0] = __nv_bfloat162(l0, l1);
    lp[2 * i + 1] = __nv_bfloat162(l2, l3);
}

// ---------------------------------------------------------------------------
// HMMA split-bf16 GEMM — EXACT R13 (passing, fastest) version.
// 128x64 CTA tile, 128 threads (4 warps, each 32x64), static smem, 4 CTA hint.
// MODE 0: QKV -> bf16 hi/lo: Q(*0.125)/K as [bh][t][dh]; V TRANSPOSED [bh][d][t].
// MODE 1: out-proj -> fp32 d_out.
// ---------------------------------------------------------------------------
#define BK     32
#define PITCH  80
#define ABUF   (128 * PITCH)   // 10240
#define BBUF   (64 * PITCH)    // 5120

template<int MODE>
__global__ __launch_bounds__(128, 4) void hmma_gemm_kernel(
    const __nv_bfloat16* __restrict__ Ahi, const __nv_bfloat16* __restrict__ Alo,
    const __nv_bfloat16* __restrict__ Bhi, const __nv_bfloat16* __restrict__ Blo,
    const float* __restrict__ bias, float* __restrict__ out)
{
    __shared__ char smem[2 * ABUF + 2 * BBUF];   // 30720 bytes
    char* sAh = smem;
    char* sAl = smem + ABUF;
    char* sBh = smem + 2 * ABUF;
    char* sBl = smem + 2 * ABUF + BBUF;

    const int tid  = threadIdx.x;
    const int wid  = tid >> 5;
    const int lane = tid & 31;
    const int rowBase = blockIdx.y * 128;
    const int colBase = blockIdx.x * 64;

    const uint32_t sb_Ah = smem_u32(sAh);
    const uint32_t sb_Al = smem_u32(sAl);
    const uint32_t sb_Bh = smem_u32(sBh);
    const uint32_t sb_Bl = smem_u32(sBl);

    float acc[2][8][4];
#pragma unroll
    for (int i = 0; i < 2; i++)
#pragma unroll
        for (int j = 0; j < 8; j++)
#pragma unroll
            for (int k = 0; k < 4; k++) acc[i][j][k] = 0.0f;

    const uint32_t aoff = (uint32_t)((wid * 32 + (lane & 15)) * PITCH + (lane >> 4) * 16);
    const uint32_t boff = (uint32_t)(((lane >> 4) * 8 + (lane & 7)) * PITCH +
                                     ((lane >> 3) & 1) * 16);

    for (int k0 = 0; k0 < E_DIM; k0 += BK) {
        __syncthreads();
#pragma unroll
        for (int s = 0; s < 4; s++) {
            int unit = tid + s * 128;
            int row = unit >> 2, seg = unit & 3;
            uint32_t so = (uint32_t)(row * PITCH + seg * 16);
            size_t ao = (size_t)(rowBase + row) * E_DIM + k0 + seg * 8;
            *reinterpret_cast<uint4*>(sAh + so) = *reinterpret_cast<const uint4*>(Ahi + ao);
            *reinterpret_cast<uint4*>(sAl + so) = *reinterpret_cast<const uint4*>(Alo + ao);
        }
#pragma unroll
        for (int s = 0; s < 2; s++) {
            int unit = tid + s * 128;
            int row = unit >> 2, seg = unit & 3;
            uint32_t so = (uint32_t)(row * PITCH + seg * 16);
            size_t bo = (size_t)(colBase + row) * E_DIM + k0 + seg * 8;
            *reinterpret_cast<uint4*>(sBh + so) = *reinterpret_cast<const uint4*>(Bhi + bo);
            *reinterpret_cast<uint4*>(sBl + so) = *reinterpret_cast<const uint4*>(Blo + bo);
        }
        __syncthreads();

#pragma unroll
        for (int ks = 0; ks < BK; ks += 16) {
            const uint32_t kb = (uint32_t)(ks * 2);
            uint32_t ah[2][4], al[2][4];
#pragma unroll
            for (int mt = 0; mt < 2; mt++) {
                uint32_t ar = aoff + (uint32_t)(mt * 16 * PITCH) + kb;
                ldsm_x4(ah[mt][0], ah[mt][1], ah[mt][2], ah[mt][3], sb_Ah + ar);
                ldsm_x4(al[mt][0], al[mt][1], al[mt][2], al[mt][3], sb_Al + ar);
            }
#pragma unroll
            for (int np = 0; np < 4; np++) {
                uint32_t br = boff + (uint32_t)(np * 16 * PITCH) + kb;
                uint32_t bh[4], bl[4];
                ldsm_x4(bh[0], bh[1], bh[2], bh[3], sb_Bh + br);
                ldsm_x4(bl[0], bl[1], bl[2], bl[3], sb_Bl + br);
#pragma unroll
                for (int mt = 0; mt < 2; mt++) {
#pragma unroll
                    for (int j = 0; j < 2; j++) {
                        float* d = acc[mt][np * 2 + j];
                        mma_bf16(d, ah[mt], &bh[j * 2]);
                        mma_bf16(d, ah[mt], &bl[j * 2]);
                        mma_bf16(d, al[mt], &bh[j * 2]);
                    }
                }
            }
        }
    }

    const int rloc = wid * 32 + (lane >> 2);

    if (MODE == 0) {
        const int f0 = colBase;
        const int which = f0 >> 10;
        const int h = (f0 & 1023) >> 6;
        if (which < 2) {
            __nv_bfloat16* dsth = (which == 0) ? g_Qh : g_Kh;
            __nv_bfloat16* dstl = (which == 0) ? g_Ql : g_Kl;
            const float scale = (which == 0) ? 0.125f : 1.0f;
#pragma unroll
            for (int mt = 0; mt < 2; mt++) {
#pragma unroll
                for (int half = 0; half < 2; half++) {
                    int r = rowBase + rloc + mt * 16 + half * 8;
                    int t = r >> 1, bb = r & 1;
                    size_t rb = ((size_t)(bb * H_DIM + h) * T_DIM + t) * DH;
#pragma unroll
                    for (int nt = 0; nt < 8; nt++) {
                        int d = nt * 8 + (lane & 3) * 2;
                        float v0 = (acc[mt][nt][half * 2 + 0] + bias[f0 + d])     * scale;
                        float v1 = (acc[mt][nt][half * 2 + 1] + bias[f0 + d + 1]) * scale;
                        float ra, rbf;
                        uint32_t hh = pack_hi2(v0, v1, ra, rbf);
                        *reinterpret_cast<uint32_t*>(&dsth[rb + d]) = hh;
                        *reinterpret_cast<uint32_t*>(&dstl[rb + d]) = pack2(ra, rbf);
                    }
                }
            }
        } else {
#pragma unroll
            for (int mt = 0; mt < 2; mt++) {
#pragma unroll
                for (int half = 0; half < 2; half++) {
                    int r = rowBase + rloc + mt * 16 + half * 8;
                    int t = r >> 1, bb = r & 1;
                    size_t cb = (size_t)(bb * H_DIM + h) * DH * T_DIM;
#pragma unroll
                    for (int nt = 0; nt < 8; nt++) {
                        int d = nt * 8 + (lane & 3) * 2;
#pragma unroll
                        for (int e = 0; e < 2; e++) {
                            float v = acc[mt][nt][half * 2 + e] + bias[f0 + d + e];
                            __nv_bfloat16 vh = __float2bfloat16(v);
                            __nv_bfloat16 vl = __float2bfloat16(v - __bfloat162float(vh));
                            size_t idx = cb + (size_t)(d + e) * T_DIM + t;
                            g_Vth[idx] = vh;
                            g_Vtl[idx] = vl;
                        }
                    }
                }
            }
        }
    } else {
#pragma unroll
        for (int mt = 0; mt < 2; mt++) {
#pragma unroll
            for (int half = 0; half < 2; half++) {
                int r = rowBase + rloc + mt * 16 + half * 8;
                float* dst = out + (size_t)r * E_DIM;
#pragma unroll
                for (int nt = 0; nt < 8; nt++) {
                    int c = colBase + nt * 8 + (lane & 3) * 2;
                    float2 v;
                    v.x = acc[mt][nt][half * 2 + 0] + bias[c];
                    v.y = acc[mt][nt][half * 2 + 1] + bias[c + 1];
                    *reinterpret_cast<float2*>(dst + c) = v;
                }
            }
        }
    }
}

// ---------------------------------------------------------------------------
// Kernel 2: HMMA flash attention — BM=128, 4 warps, 32 q-rows (2 m-tiles)
// per warp. K-fragments reused across both m-tiles in the S stage;
// K/V staging per chip halves (half as many CTAs). PV loops mt-outer to
// keep P fragments at 32 live registers.
// ---------------------------------------------------------------------------
#define FPITCH 72
#define FPB    (FPITCH * 2)          // 144 bytes/row
#define FBUF   (64 * FPB)            // 9216 bytes
#define QBUF   (128 * FPB)           // 18432 bytes
#define FSMEM  (2 * QBUF + 4 * FBUF) // 73728 bytes

__global__ __launch_bounds__(128) void flash_hmma_kernel()
{
    extern __shared__ char fsm[];
    char* sQh = fsm;                         // + QBUF = sQl
    char* sKh = fsm + 2 * QBUF;
    char* sKl = fsm + 2 * QBUF + FBUF;
    char* sVt = fsm + 2 * QBUF + 2 * FBUF;
    char* sVl = fsm + 2 * QBUF + 3 * FBUF;

    const int tid = threadIdx.x;
    const int lane = tid & 31;
    const int w = tid >> 5;
    const int bh = blockIdx.x;
    const int q0 = blockIdx.y * 128;

    const size_t hbase = (size_t)bh * T_DIM * DH;
    const __nv_bfloat16* Qhg = g_Qh + hbase;
    const __nv_bfloat16* Qlg = g_Ql + hbase;
    const __nv_bfloat16* Khg = g_Kh + hbase;
    const __nv_bfloat16* Klg = g_Kl + hbase;
    const __nv_bfloat16* Vthg = g_Vth + (size_t)bh * DH * T_DIM;
    const __nv_bfloat16* Vtlg = g_Vtl + (size_t)bh * DH * T_DIM;

    // Stage Q tile (128 rows, hi/lo): pure copies, 8 units/thread
#pragma unroll
    for (int s = 0; s < 8; s++) {
        int unit = tid + s * 128;            // 0..1023
        int row = unit >> 3, seg = unit & 7;
        int go = (q0 + row) * DH + seg * 8;
        uint32_t so = (uint32_t)(row * FPB + seg * 16);
        *reinterpret_cast<uint4*>(sQh + so)        = *reinterpret_cast<const uint4*>(Qhg + go);
        *reinterpret_cast<uint4*>(sQh + QBUF + so) = *reinterpret_cast<const uint4*>(Qlg + go);
    }
    __syncthreads();

    // Persistent Q A-fragments: 2 m-tiles x 4 k-steps x hi/lo
    uint32_t aqh[2][4][4], aql[2][4][4];
#pragma unroll
    for (int mt = 0; mt < 2; mt++) {
        uint32_t qaddr = smem_u32(sQh) +
            (uint32_t)((w * 32 + mt * 16 + (lane & 15)) * FPB + (lane >> 4) * 16);
#pragma unroll
        for (int ks = 0; ks < 4; ks++) {
            ldsm_x4(aqh[mt][ks][0], aqh[mt][ks][1], aqh[mt][ks][2], aqh[mt][ks][3],
                    qaddr + ks * 32);
            ldsm_x4(aql[mt][ks][0], aql[mt][ks][1], aql[mt][ks][2], aql[mt][ks][3],
                    qaddr + QBUF + ks * 32);
        }
    }

    float o[2][8][4];
#pragma unroll
    for (int mt = 0; mt < 2; mt++)
#pragma unroll
        for (int i = 0; i < 8; i++)
#pragma unroll
            for (int j = 0; j < 4; j++) o[mt][i][j] = 0.0f;
    float m1[2] = {-1e30f, -1e30f}, m2[2] = {-1e30f, -1e30f};
    float l1[2] = {0.0f, 0.0f},     l2[2] = {0.0f, 0.0f};

    const uint32_t blanes = (uint32_t)(((lane >> 4) * 8 + (lane & 7)) * FPB +
                                       ((lane >> 3) & 1) * 16);
    const uint32_t kaddr = smem_u32(sKh) + blanes;
    const uint32_t vaddr = smem_u32(sVt) + blanes;

    for (int kt = 0; kt < T_DIM; kt += 64) {
        __syncthreads();
        // Stage K (rows=key) and Vt (rows=d): 512 units, 4/thread
#pragma unroll
        for (int s = 0; s < 4; s++) {
            int unit = tid + s * 128;
            int row = unit >> 3, seg = unit & 7;
            uint32_t so = (uint32_t)(row * FPB + seg * 16);
            int gk = (kt + row) * DH + seg * 8;
            int gv = row * T_DIM + kt + seg * 8;
            *reinterpret_cast<uint4*>(sKh + so) = *reinterpret_cast<const uint4*>(Khg + gk);
            *reinterpret_cast<uint4*>(sKl + so) = *reinterpret_cast<const uint4*>(Klg + gk);
            *reinterpret_cast<uint4*>(sVt + so) = *reinterpret_cast<const uint4*>(Vthg + gv);
            *reinterpret_cast<uint4*>(sVl + so) = *reinterpret_cast<const uint4*>(Vtlg + gv);
        }
        __syncthreads();

        // S = Q K^T (warp: 32 q-rows x 64 keys; K-frags reused across mt)
        float s4[2][8][4];
#pragma unroll
        for (int mt = 0; mt < 2; mt++)
#pragma unroll
            for (int i = 0; i < 8; i++)
#pragma unroll
                for (int j = 0; j < 4; j++) s4[mt][i][j] = 0.0f;

#pragma unroll
        for (int ks = 0; ks < 4; ks++) {
#pragma unroll
            for (int np = 0; np < 4; np++) {
                uint32_t ba = kaddr + (uint32_t)(np * 16 * FPB) + ks * 32;
                uint32_t bhf[4], blf[4];
                ldsm_x4(bhf[0], bhf[1], bhf[2], bhf[3], ba);
                ldsm_x4(blf[0], blf[1], blf[2], blf[3], ba + FBUF);
#pragma unroll
                for (int mt = 0; mt < 2; mt++) {
#pragma unroll
                    for (int j = 0; j < 2; j++) {
                        float* d = s4[mt][np * 2 + j];
                        mma_bf16(d, aqh[mt][ks], &bhf[j * 2]);
                        mma_bf16(d, aqh[mt][ks], &blf[j * 2]);
                        mma_bf16(d, aql[mt][ks], &bhf[j * 2]);
                    }
                }
            }
        }

        // Per m-tile: softmax, pack P, PV (V-frags re-read per mt)
#pragma unroll
        for (int mt = 0; mt < 2; mt++) {
            float mx1 = -1e30f, mx2 = -1e30f;
#pragma unroll
            for (int nt = 0; nt < 8; nt++) {
                mx1 = fmaxf(mx1, fmaxf(s4[mt][nt][0], s4[mt][nt][1]));
                mx2 = fmaxf(mx2, fmaxf(s4[mt][nt][2], s4[mt][nt][3]));
            }
            mx1 = fmaxf(mx1, __shfl_xor_sync(0xffffffffu, mx1, 1));
            mx1 = fmaxf(mx1, __shfl_xor_sync(0xffffffffu, mx1, 2));
            mx2 = fmaxf(mx2, __shfl_xor_sync(0xffffffffu, mx2, 1));
            mx2 = fmaxf(mx2, __shfl_xor_sync(0xffffffffu, mx2, 2));

            float mn1 = fmaxf(m1[mt], mx1), mn2 = fmaxf(m2[mt], mx2);
            float c1 = __expf(m1[mt] - mn1), c2 = __expf(m2[mt] - mn2);
            m1[mt] = mn1; m2[mt] = mn2;

            float p1 = 0.0f, p2 = 0.0f;
#pragma unroll
            for (int nt = 0; nt < 8; nt++) {
                s4[mt][nt][0] = __expf(s4[mt][nt][0] - mn1); p1 += s4[mt][nt][0];
                s4[mt][nt][1] = __expf(s4[mt][nt][1] - mn1); p1 += s4[mt][nt][1];
                s4[mt][nt][2] = __expf(s4[mt][nt][2] - mn2); p2 += s4[mt][nt][2];
                s4[mt][nt][3] = __expf(s4[mt][nt][3] - mn2); p2 += s4[mt][nt][3];
            }
            l1[mt] = l1[mt] * c1 + p1;
            l2[mt] = l2[mt] * c2 + p2;
#pragma unroll
            for (int nt = 0; nt < 8; nt++) {
                o[mt][nt][0] *= c1; o[mt][nt][1] *= c1;
                o[mt][nt][2] *= c2; o[mt][nt][3] *= c2;
            }

            // Pack P as A-fragments (C->A identity), hi/lo
            uint32_t ph[4][4], pl[4][4];
#pragma unroll
            for (int ks = 0; ks < 4; ks++) {
                float ra, rb;
                ph[ks][0] = pack_hi2(s4[mt][2 * ks][0],     s4[mt][2 * ks][1],     ra, rb);
                pl[ks][0] = pack2(ra, rb);
                ph[ks][1] = pack_hi2(s4[mt][2 * ks][2],     s4[mt][2 * ks][3],     ra, rb);
                pl[ks][1] = pack2(ra, rb);
                ph[ks][2] = pack_hi2(s4[mt][2 * ks + 1][0], s4[mt][2 * ks + 1][1], ra, rb);
                pl[ks][2] = pack2(ra, rb);
                ph[ks][3] = pack_hi2(s4[mt][2 * ks + 1][2], s4[mt][2 * ks + 1][3], ra, rb);
                pl[ks][3] = pack2(ra, rb);
            }

            // O += P V
#pragma unroll
            for (int ks = 0; ks < 4; ks++) {
#pragma unroll
                for (int np = 0; np < 4; np++) {
                    uint32_t ba = vaddr + (uint32_t)(np * 16 * FPB) + ks * 32;
                    uint32_t bvh[4], bvl[4];
                    ldsm_x4(bvh[0], bvh[1], bvh[2], bvh[3], ba);
                    ldsm_x4(bvl[0], bvl[1], bvl[2], bvl[3], ba + FBUF);
#pragma unroll
                    for (int j = 0; j < 2; j++) {
                        float* d = o[mt][np * 2 + j];
                        mma_bf16(d, ph[ks], &bvh[j * 2]);
                        mma_bf16(d, ph[ks], &bvl[j * 2]);
                        mma_bf16(d, pl[ks], &bvh[j * 2]);
                    }
                }
            }
        }
    }

    // Epilogue per m-tile
    const int b = bh >> 4;
    const int h = bh & 15;
#pragma unroll
    for (int mt = 0; mt < 2; mt++) {
        float L1 = l1[mt], L2 = l2[mt];
        L1 += __shfl_xor_sync(0xffffffffu, L1, 1);
        L1 += __shfl_xor_sync(0xffffffffu, L1, 2);
        L2 += __shfl_xor_sync(0xffffffffu, L2, 1);
        L2 += __shfl_xor_sync(0xffffffffu, L2, 2);
        const float inv1 = 1.0f / L1, inv2 = 1.0f / L2;

        const int r1 = q0 + w * 32 + mt * 16 + (lane >> 2);
        const int r2 = r1 + 8;
#pragma unroll
        for (int nt = 0; nt < 8; nt++) {
            int d = nt * 8 + (lane & 3) * 2;
            float ra, rb;
            uint32_t hh = pack_hi2(o[mt][nt][0] * inv1, o[mt][nt][1] * inv1, ra, rb);
            size_t i1 = ((size_t)r1 * B_DIM + b) * E_DIM + h * DH + d;
            *reinterpret_cast<uint32_t*>(&g_Ahi[i1]) = hh;
            *reinterpret_cast<uint32_t*>(&g_Alo[i1]) = pack2(ra, rb);
            hh = pack_hi2(o[mt][nt][2] * inv2, o[mt][nt][3] * inv2, ra, rb);
            size_t i2 = ((size_t)r2 * B_DIM + b) * E_DIM + h * DH + d;
            *reinterpret_cast<uint32_t*>(&g_Ahi[i2]) = hh;
            *reinterpret_cast<uint32_t*>(&g_Alo[i2]) = pack2(ra, rb);
        }
    }
}

// ---------------------------------------------------------------------------
// Launch
// ---------------------------------------------------------------------------
extern "C" void kernel_launch(void* const* d_in, const int* in_sizes, int n_in,
                              void* d_out, int out_size)
{
    const float* query = (const float*)d_in[0];
    const float* in_w  = (const float*)d_in[3];
    const float* in_b  = (const float*)d_in[4];
    const float* out_w = (const float*)d_in[5];
    const float* out_b = (const float*)d_in[6];
    float* out = (float*)d_out;

    __nv_bfloat16 *xhi, *xlo, *whi, *wlo, *owhi, *owlo, *ahi, *alo;
    cudaGetSymbolAddress((void**)&xhi,  g_Xhi);  cudaGetSymbolAddress((void**)&xlo,  g_Xlo);
    cudaGetSymbolAddress((void**)&whi,  g_Whi);  cudaGetSymbolAddress((void**)&wlo,  g_Wlo);
    cudaGetSymbolAddress((void**)&owhi, g_OWhi); cudaGetSymbolAddress((void**)&owlo, g_OWlo);
    cudaGetSymbolAddress((void**)&ahi,  g_Ahi);  cudaGetSymbolAddress((void**)&alo,  g_Alo);

    // 0) fp32 -> bf16 hi/lo splits
    cvt_split_kernel<<<(TB * E_DIM / 4 + 255) / 256, 256>>>(query, xhi, xlo, TB * E_DIM / 4);
    cvt_split_kernel<<<(E3 * E_DIM / 4 + 255) / 256, 256>>>(in_w, whi, wlo, E3 * E_DIM / 4);
    cvt_split_kernel<<<(E_DIM * E_DIM / 4 + 255) / 256, 256>>>(out_w, owhi, owlo, E_DIM * E_DIM / 4);

    // 1) QKV projection via HMMA (exact R13)
    hmma_gemm_kernel<0><<<dim3(E3 / 64, TB / 128), 128>>>(xhi, xlo, whi, wlo, in_b, nullptr);

    // 2) HMMA flash attention (BM=128, K-frag reuse)
    cudaFuncSetAttribute(flash_hmma_kernel,
                         cudaFuncAttributeMaxDynamicSharedMemorySize, FSMEM);
    flash_hmma_kernel<<<dim3(B_DIM * H_DIM, T_DIM / 128), 128, FSMEM>>>();

    // 3) Output projection via HMMA (exact R13)
    hmma_gemm_kernel<1><<<dim3(E_DIM / 64, TB / 128), 128>>>(ahi, alo, owhi, owlo, out_b, out);
}

// round 16
// speedup vs baseline: 1.0524x; 1.0524x over previous
#include <cuda_runtime.h>
#include <cuda_bf16.h>
#include <cstdint>

// Problem constants
#define T_DIM 2048
#define B_DIM 2
#define E_DIM 1024
#define H_DIM 16
#define DH    64
#define TB    (T_DIM * B_DIM)   // 4096
#define E3    (3 * E_DIM)       // 3072

// ---------------------------------------------------------------------------
// Device scratch (no runtime allocation allowed)
// ---------------------------------------------------------------------------
__device__ __nv_bfloat16 g_Qh[B_DIM * H_DIM * T_DIM * DH], g_Ql[B_DIM * H_DIM * T_DIM * DH];
__device__ __nv_bfloat16 g_Kh[B_DIM * H_DIM * T_DIM * DH], g_Kl[B_DIM * H_DIM * T_DIM * DH];
// V stored TRANSPOSED: [bh][d][t]
__device__ __nv_bfloat16 g_Vth[B_DIM * H_DIM * DH * T_DIM], g_Vtl[B_DIM * H_DIM * DH * T_DIM];

__device__ __nv_bfloat16 g_Xhi[TB * E_DIM],  g_Xlo[TB * E_DIM];        // query split
__device__ __nv_bfloat16 g_Whi[E3 * E_DIM],  g_Wlo[E3 * E_DIM];        // in_proj_weight split
__device__ __nv_bfloat16 g_OWhi[E_DIM * E_DIM], g_OWlo[E_DIM * E_DIM]; // out_w split
__device__ __nv_bfloat16 g_Ahi[TB * E_DIM],  g_Alo[TB * E_DIM];        // attn output split

// ---------------------------------------------------------------------------
// Helpers (proven)
// ---------------------------------------------------------------------------
__device__ __forceinline__ uint32_t smem_u32(const void* p) {
    uint32_t a;
    asm("{ .reg .u64 t; cvta.to.shared.u64 t, %1; cvt.u32.u64 %0, t; }" : "=r"(a) : "l"(p));
    return a;
}

__device__ __forceinline__ void ldsm_x4(uint32_t& r0, uint32_t& r1, uint32_t& r2,
                                        uint32_t& r3, uint32_t addr) {
    asm volatile("ldmatrix.sync.aligned.m8n8.x4.shared.b16 {%0,%1,%2,%3}, [%4];"
                 : "=r"(r0), "=r"(r1), "=r"(r2), "=r"(r3) : "r"(addr));
}

__device__ __forceinline__ void mma_bf16(float* d, const uint32_t* a, const uint32_t* b) {
    asm volatile(
        "mma.sync.aligned.m16n8k16.row.col.f32.bf16.bf16.f32 "
        "{%0,%1,%2,%3}, {%4,%5,%6,%7}, {%8,%9}, {%0,%1,%2,%3};"
        : "+f"(d[0]), "+f"(d[1]), "+f"(d[2]), "+f"(d[3])
        : "r"(a[0]), "r"(a[1]), "r"(a[2]), "r"(a[3]), "r"(b[0]), "r"(b[1]));
}

__device__ __forceinline__ uint32_t pack2(float a, float b) {
    __nv_bfloat162 p(__float2bfloat16(a), __float2bfloat16(b));
    return *reinterpret_cast<uint32_t*>(&p);
}
__device__ __forceinline__ uint32_t pack_hi2(float a, float b, float& ra, float& rb) {
    __nv_bfloat16 ha = __float2bfloat16(a), hb = __float2bfloat16(b);
    ra = a - __bfloat162float(ha);
    rb = b - __bfloat162float(hb);
    __nv_bfloat162 p(ha, hb);
    return *reinterpret_cast<uint32_t*>(&p);
}

// ---------------------------------------------------------------------------
// Kernel 0: fp32 -> (bf16 hi, bf16 lo) split conversion (proven)
// ---------------------------------------------------------------------------
__global__ __launch_bounds__(256) void cvt_split_kernel(
    const float* __restrict__ x, __nv_bfloat16* __restrict__ hi,
    __nv_bfloat16* __restrict__ lo, int n4)
{
    int i = blockIdx.x * blockDim.x + threadIdx.x;
    if (i >= n4) return;
    float4 v = reinterpret_cast<const float4*>(x)[i];
    __nv_bfloat16 h0 = __float2bfloat16(v.x), h1 = __float2bfloat16(v.y);
    __nv_bfloat16 h2 = __float2bfloat16(v.z), h3 = __float2bfloat16(v.w);
    __nv_bfloat16 l0 = __float2bfloat16(v.x - __bfloat162float(h0));
    __nv_bfloat16 l1 = __float2bfloat16(v.y - __bfloat162float(h1));
    __nv_bfloat16 l2 = __float2bfloat16(v.z - __bfloat162float(h2));
    __nv_bfloat16 l3 = __float2bfloat16(v.w - __bfloat162float(h3));
    __nv_bfloat162* hp = reinterpret_cast<__nv_bfloat162*>(hi);
    __nv_bfloat162* lp = reinterpret_cast<__nv_bfloat162*>(lo);
    hp[2 * i + 0] = __nv_bfloat162(h0, h1);
    hp[2 * i + 1] = __nv_bfloat162(h2, h3);
    lp[2 * i + 0] = __nv_bfloat162(l0, l1);
    lp[2 * i + 1] = __nv_bfloat162(l2, l3);
}

// ---------------------------------------------------------------------------
// HMMA split-bf16 GEMM — EXACT R13 (passing, fastest) version, unchanged.
// ---------------------------------------------------------------------------
#define BK     32
#define PITCH  80
#define ABUF   (128 * PITCH)   // 10240
#define BBUF   (64 * PITCH)    // 5120

template<int MODE>
__global__ __launch_bounds__(128, 4) void hmma_gemm_kernel(
    const __nv_bfloat16* __restrict__ Ahi, const __nv_bfloat16* __restrict__ Alo,
    const __nv_bfloat16* __restrict__ Bhi, const __nv_bfloat16* __restrict__ Blo,
    const float* __restrict__ bias, float* __restrict__ out)
{
    __shared__ char smem[2 * ABUF + 2 * BBUF];   // 30720 bytes
    char* sAh = smem;
    char* sAl = smem + ABUF;
    char* sBh = smem + 2 * ABUF;
    char* sBl = smem + 2 * ABUF + BBUF;

    const int tid  = threadIdx.x;
    const int wid  = tid >> 5;
    const int lane = tid & 31;
    const int rowBase = blockIdx.y * 128;
    const int colBase = blockIdx.x * 64;

    const uint32_t sb_Ah = smem_u32(sAh);
    const uint32_t sb_Al = smem_u32(sAl);
    const uint32_t sb_Bh = smem_u32(sBh);
    const uint32_t sb_Bl = smem_u32(sBl);

    float acc[2][8][4];
#pragma unroll
    for (int i = 0; i < 2; i++)
#pragma unroll
        for (int j = 0; j < 8; j++)
#pragma unroll
            for (int k = 0; k < 4; k++) acc[i][j][k] = 0.0f;

    const uint32_t aoff = (uint32_t)((wid * 32 + (lane & 15)) * PITCH + (lane >> 4) * 16);
    const uint32_t boff = (uint32_t)(((lane >> 4) * 8 + (lane & 7)) * PITCH +
                                     ((lane >> 3) & 1) * 16);

    for (int k0 = 0; k0 < E_DIM; k0 += BK) {
        __syncthreads();
#pragma unroll
        for (int s = 0; s < 4; s++) {
            int unit = tid + s * 128;
            int row = unit >> 2, seg = unit & 3;
            uint32_t so = (uint32_t)(row * PITCH + seg * 16);
            size_t ao = (size_t)(rowBase + row) * E_DIM + k0 + seg * 8;
            *reinterpret_cast<uint4*>(sAh + so) = *reinterpret_cast<const uint4*>(Ahi + ao);
            *reinterpret_cast<uint4*>(sAl + so) = *reinterpret_cast<const uint4*>(Alo + ao);
        }
#pragma unroll
        for (int s = 0; s < 2; s++) {
            int unit = tid + s * 128;
            int row = unit >> 2, seg = unit & 3;
            uint32_t so = (uint32_t)(row * PITCH + seg * 16);
            size_t bo = (size_t)(colBase + row) * E_DIM + k0 + seg * 8;
            *reinterpret_cast<uint4*>(sBh + so) = *reinterpret_cast<const uint4*>(Bhi + bo);
            *reinterpret_cast<uint4*>(sBl + so) = *reinterpret_cast<const uint4*>(Blo + bo);
        }
        __syncthreads();

#pragma unroll
        for (int ks = 0; ks < BK; ks += 16) {
            const uint32_t kb = (uint32_t)(ks * 2);
            uint32_t ah[2][4], al[2][4];
#pragma unroll
            for (int mt = 0; mt < 2; mt++) {
                uint32_t ar = aoff + (uint32_t)(mt * 16 * PITCH) + kb;
                ldsm_x4(ah[mt][0], ah[mt][1], ah[mt][2], ah[mt][3], sb_Ah + ar);
                ldsm_x4(al[mt][0], al[mt][1], al[mt][2], al[mt][3], sb_Al + ar);
            }
#pragma unroll
            for (int np = 0; np < 4; np++) {
                uint32_t br = boff + (uint32_t)(np * 16 * PITCH) + kb;
                uint32_t bh[4], bl[4];
                ldsm_x4(bh[0], bh[1], bh[2], bh[3], sb_Bh + br);
                ldsm_x4(bl[0], bl[1], bl[2], bl[3], sb_Bl + br);
#pragma unroll
                for (int mt = 0; mt < 2; mt++) {
#pragma unroll
                    for (int j = 0; j < 2; j++) {
                        float* d = acc[mt][np * 2 + j];
                        mma_bf16(d, ah[mt], &bh[j * 2]);
                        mma_bf16(d, ah[mt], &bl[j * 2]);
                        mma_bf16(d, al[mt], &bh[j * 2]);
                    }
                }
            }
        }
    }

    const int rloc = wid * 32 + (lane >> 2);

    if (MODE == 0) {
        const int f0 = colBase;
        const int which = f0 >> 10;
        const int h = (f0 & 1023) >> 6;
        if (which < 2) {
            __nv_bfloat16* dsth = (which == 0) ? g_Qh : g_Kh;
            __nv_bfloat16* dstl = (which == 0) ? g_Ql : g_Kl;
            const float scale = (which == 0) ? 0.125f : 1.0f;
#pragma unroll
            for (int mt = 0; mt < 2; mt++) {
#pragma unroll
                for (int half = 0; half < 2; half++) {
                    int r = rowBase + rloc + mt * 16 + half * 8;
                    int t = r >> 1, bb = r & 1;
                    size_t rb = ((size_t)(bb * H_DIM + h) * T_DIM + t) * DH;
#pragma unroll
                    for (int nt = 0; nt < 8; nt++) {
                        int d = nt * 8 + (lane & 3) * 2;
                        float v0 = (acc[mt][nt][half * 2 + 0] + bias[f0 + d])     * scale;
                        float v1 = (acc[mt][nt][half * 2 + 1] + bias[f0 + d + 1]) * scale;
                        float ra, rbf;
                        uint32_t hh = pack_hi2(v0, v1, ra, rbf);
                        *reinterpret_cast<uint32_t*>(&dsth[rb + d]) = hh;
                        *reinterpret_cast<uint32_t*>(&dstl[rb + d]) = pack2(ra, rbf);
                    }
                }
            }
        } else {
#pragma unroll
            for (int mt = 0; mt < 2; mt++) {
#pragma unroll
                for (int half = 0; half < 2; half++) {
                    int r = rowBase + rloc + mt * 16 + half * 8;
                    int t = r >> 1, bb = r & 1;
                    size_t cb = (size_t)(bb * H_DIM + h) * DH * T_DIM;
#pragma unroll
                    for (int nt = 0; nt < 8; nt++) {
                        int d = nt * 8 + (lane & 3) * 2;
#pragma unroll
                        for (int e = 0; e < 2; e++) {
                            float v = acc[mt][nt][half * 2 + e] + bias[f0 + d + e];
                            __nv_bfloat16 vh = __float2bfloat16(v);
                            __nv_bfloat16 vl = __float2bfloat16(v - __bfloat162float(vh));
                            size_t idx = cb + (size_t)(d + e) * T_DIM + t;
                            g_Vth[idx] = vh;
                            g_Vtl[idx] = vl;
                        }
                    }
                }
            }
        }
    } else {
#pragma unroll
        for (int mt = 0; mt < 2; mt++) {
#pragma unroll
            for (int half = 0; half < 2; half++) {
                int r = rowBase + rloc + mt * 16 + half * 8;
                float* dst = out + (size_t)r * E_DIM;
#pragma unroll
                for (int nt = 0; nt < 8; nt++) {
                    int c = colBase + nt * 8 + (lane & 3) * 2;
                    float2 v;
                    v.x = acc[mt][nt][half * 2 + 0] + bias[c];
                    v.y = acc[mt][nt][half * 2 + 1] + bias[c + 1];
                    *reinterpret_cast<float2*>(dst + c) = v;
                }
            }
        }
    }
}

// ---------------------------------------------------------------------------
// Kernel 2: HMMA flash attention — BM=128 with 8 WARPS (256 threads).
// Per-warp state and instruction stream IDENTICAL to R13 (16 q-rows/warp);
// one CTA's staged K/V serves 2x the q-rows -> chip staging traffic halves.
// ---------------------------------------------------------------------------
#define FPITCH 72
#define FPB    (FPITCH * 2)          // 144 bytes/row
#define FBUF   (64 * FPB)            // 9216 bytes
#define QBUF   (128 * FPB)           // 18432 bytes
#define FSMEM  (2 * QBUF + 4 * FBUF) // 73728 bytes

__global__ __launch_bounds__(256) void flash_hmma_kernel()
{
    extern __shared__ char fsm[];
    char* sQh = fsm;                         // + QBUF = sQl
    char* sKh = fsm + 2 * QBUF;
    char* sKl = fsm + 2 * QBUF + FBUF;
    char* sVt = fsm + 2 * QBUF + 2 * FBUF;
    char* sVl = fsm + 2 * QBUF + 3 * FBUF;

    const int tid = threadIdx.x;
    const int lane = tid & 31;
    const int w = tid >> 5;                  // 0..7 -> 16 q-rows each
    const int bh = blockIdx.x;
    const int q0 = blockIdx.y * 128;

    const size_t hbase = (size_t)bh * T_DIM * DH;
    const __nv_bfloat16* Qhg = g_Qh + hbase;
    const __nv_bfloat16* Qlg = g_Ql + hbase;
    const __nv_bfloat16* Khg = g_Kh + hbase;
    const __nv_bfloat16* Klg = g_Kl + hbase;
    const __nv_bfloat16* Vthg = g_Vth + (size_t)bh * DH * T_DIM;
    const __nv_bfloat16* Vtlg = g_Vtl + (size_t)bh * DH * T_DIM;

    // Stage Q tile (128 rows, hi/lo): 1024 units / 256 threads = 4 each
#pragma unroll
    for (int s = 0; s < 4; s++) {
        int unit = tid + s * 256;
        int row = unit >> 3, seg = unit & 7;
        int go = (q0 + row) * DH + seg * 8;
        uint32_t so = (uint32_t)(row * FPB + seg * 16);
        *reinterpret_cast<uint4*>(sQh + so)        = *reinterpret_cast<const uint4*>(Qhg + go);
        *reinterpret_cast<uint4*>(sQh + QBUF + so) = *reinterpret_cast<const uint4*>(Qlg + go);
    }
    __syncthreads();

    // Persistent Q A-fragments (R13 per-warp footprint)
    uint32_t aqh[4][4], aql[4][4];
    const uint32_t qaddr = smem_u32(sQh) +
        (uint32_t)((w * 16 + (lane & 15)) * FPB + (lane >> 4) * 16);
#pragma unroll
    for (int ks = 0; ks < 4; ks++) {
        ldsm_x4(aqh[ks][0], aqh[ks][1], aqh[ks][2], aqh[ks][3], qaddr + ks * 32);
        ldsm_x4(aql[ks][0], aql[ks][1], aql[ks][2], aql[ks][3], qaddr + QBUF + ks * 32);
    }

    float o[8][4];
#pragma unroll
    for (int i = 0; i < 8; i++)
#pragma unroll
        for (int j = 0; j < 4; j++) o[i][j] = 0.0f;
    float m1 = -1e30f, m2 = -1e30f, l1 = 0.0f, l2 = 0.0f;

    const uint32_t blanes = (uint32_t)(((lane >> 4) * 8 + (lane & 7)) * FPB +
                                       ((lane >> 3) & 1) * 16);
    const uint32_t kaddr = smem_u32(sKh) + blanes;
    const uint32_t vaddr = smem_u32(sVt) + blanes;

    for (int kt = 0; kt < T_DIM; kt += 64) {
        __syncthreads();
        // Stage K (rows=key) + Vt (rows=d): 512 units / 256 threads = 2 each
#pragma unroll
        for (int s = 0; s < 2; s++) {
            int unit = tid + s * 256;
            int row = unit >> 3, seg = unit & 7;
            uint32_t so = (uint32_t)(row * FPB + seg * 16);
            int gk = (kt + row) * DH + seg * 8;
            int gv = row * T_DIM + kt + seg * 8;
            *reinterpret_cast<uint4*>(sKh + so) = *reinterpret_cast<const uint4*>(Khg + gk);
            *reinterpret_cast<uint4*>(sKl + so) = *reinterpret_cast<const uint4*>(Klg + gk);
            *reinterpret_cast<uint4*>(sVt + so) = *reinterpret_cast<const uint4*>(Vthg + gv);
            *reinterpret_cast<uint4*>(sVl + so) = *reinterpret_cast<const uint4*>(Vtlg + gv);
        }
        __syncthreads();

        // S = Q K^T (warp: 16 q-rows x 64 keys) — R13 stream
        float s4[8][4];
#pragma unroll
        for (int i = 0; i < 8; i++)
#pragma unroll
            for (int j = 0; j < 4; j++) s4[i][j] = 0.0f;

#pragma unroll
        for (int ks = 0; ks < 4; ks++) {
#pragma unroll
            for (int np = 0; np < 4; np++) {
                uint32_t ba = kaddr + (uint32_t)(np * 16 * FPB) + ks * 32;
                uint32_t bhf[4], blf[4];
                ldsm_x4(bhf[0], bhf[1], bhf[2], bhf[3], ba);
                ldsm_x4(blf[0], blf[1], blf[2], blf[3], ba + FBUF);
#pragma unroll
                for (int j = 0; j < 2; j++) {
                    float* d = s4[np * 2 + j];
                    mma_bf16(d, aqh[ks], &bhf[j * 2]);
                    mma_bf16(d, aqh[ks], &blf[j * 2]);
                    mma_bf16(d, aql[ks], &bhf[j * 2]);
                }
            }
        }

        // Online softmax — R13
        float mx1 = -1e30f, mx2 = -1e30f;
#pragma unroll
        for (int nt = 0; nt < 8; nt++) {
            mx1 = fmaxf(mx1, fmaxf(s4[nt][0], s4[nt][1]));
            mx2 = fmaxf(mx2, fmaxf(s4[nt][2], s4[nt][3]));
        }
        mx1 = fmaxf(mx1, __shfl_xor_sync(0xffffffffu, mx1, 1));
        mx1 = fmaxf(mx1, __shfl_xor_sync(0xffffffffu, mx1, 2));
        mx2 = fmaxf(mx2, __shfl_xor_sync(0xffffffffu, mx2, 1));
        mx2 = fmaxf(mx2, __shfl_xor_sync(0xffffffffu, mx2, 2));

        float mn1 = fmaxf(m1, mx1), mn2 = fmaxf(m2, mx2);
        float c1 = __expf(m1 - mn1), c2 = __expf(m2 - mn2);
        m1 = mn1; m2 = mn2;

        float p1 = 0.0f, p2 = 0.0f;
#pragma unroll
        for (int nt = 0; nt < 8; nt++) {
            s4[nt][0] = __expf(s4[nt][0] - mn1); p1 += s4[nt][0];
            s4[nt][1] = __expf(s4[nt][1] - mn1); p1 += s4[nt][1];
            s4[nt][2] = __expf(s4[nt][2] - mn2); p2 += s4[nt][2];
            s4[nt][3] = __expf(s4[nt][3] - mn2); p2 += s4[nt][3];
        }
        l1 = l1 * c1 + p1;
        l2 = l2 * c2 + p2;
#pragma unroll
        for (int nt = 0; nt < 8; nt++) {
            o[nt][0] *= c1; o[nt][1] *= c1;
            o[nt][2] *= c2; o[nt][3] *= c2;
        }

        // Pack P as A-fragments (C->A identity), hi/lo — R13
        uint32_t ph[4][4], pl[4][4];
#pragma unroll
        for (int ks = 0; ks < 4; ks++) {
            float ra, rb;
            ph[ks][0] = pack_hi2(s4[2 * ks][0],     s4[2 * ks][1],     ra, rb);
            pl[ks][0] = pack2(ra, rb);
            ph[ks][1] = pack_hi2(s4[2 * ks][2],     s4[2 * ks][3],     ra, rb);
            pl[ks][1] = pack2(ra, rb);
            ph[ks][2] = pack_hi2(s4[2 * ks + 1][0], s4[2 * ks + 1][1], ra, rb);
            pl[ks][2] = pack2(ra, rb);
            ph[ks][3] = pack_hi2(s4[2 * ks + 1][2], s4[2 * ks + 1][3], ra, rb);
            pl[ks][3] = pack2(ra, rb);
        }

        // O += P V — R13
#pragma unroll
        for (int ks = 0; ks < 4; ks++) {
#pragma unroll
            for (int np = 0; np < 4; np++) {
                uint32_t ba = vaddr + (uint32_t)(np * 16 * FPB) + ks * 32;
                uint32_t bvh[4], bvl[4];
                ldsm_x4(bvh[0], bvh[1], bvh[2], bvh[3], ba);
                ldsm_x4(bvl[0], bvl[1], bvl[2], bvl[3], ba + FBUF);
#pragma unroll
                for (int j = 0; j < 2; j++) {
                    float* d = o[np * 2 + j];
                    mma_bf16(d, ph[ks], &bvh[j * 2]);
                    mma_bf16(d, ph[ks], &bvl[j * 2]);
                    mma_bf16(d, pl[ks], &bvh[j * 2]);
                }
            }
        }
    }

    // Epilogue — R13 with w in 0..7
    l1 += __shfl_xor_sync(0xffffffffu, l1, 1);
    l1 += __shfl_xor_sync(0xffffffffu, l1, 2);
    l2 += __shfl_xor_sync(0xffffffffu, l2, 1);
    l2 += __shfl_xor_sync(0xffffffffu, l2, 2);
    const float inv1 = 1.0f / l1, inv2 = 1.0f / l2;

    const int r1 = q0 + w * 16 + (lane >> 2);
    const int r2 = r1 + 8;
    const int b = bh >> 4;
    const int h = bh & 15;

#pragma unroll
    for (int nt = 0; nt < 8; nt++) {
        int d = nt * 8 + (lane & 3) * 2;
        float ra, rb;
        uint32_t hh = pack_hi2(o[nt][0] * inv1, o[nt][1] * inv1, ra, rb);
        size_t i1 = ((size_t)r1 * B_DIM + b) * E_DIM + h * DH + d;
        *reinterpret_cast<uint32_t*>(&g_Ahi[i1]) = hh;
        *reinterpret_cast<uint32_t*>(&g_Alo[i1]) = pack2(ra, rb);
        hh = pack_hi2(o[nt][2] * inv2, o[nt][3] * inv2, ra, rb);
        size_t i2 = ((size_t)r2 * B_DIM + b) * E_DIM + h * DH + d;
        *reinterpret_cast<uint32_t*>(&g_Ahi[i2]) = hh;
        *reinterpret_cast<uint32_t*>(&g_Alo[i2]) = pack2(ra, rb);
    }
}

// ---------------------------------------------------------------------------
// Launch
// ---------------------------------------------------------------------------
extern "C" void kernel_launch(void* const* d_in, const int* in_sizes, int n_in,
                              void* d_out, int out_size)
{
    const float* query = (const float*)d_in[0];
    const float* in_w  = (const float*)d_in[3];
    const float* in_b  = (const float*)d_in[4];
    const float* out_w = (const float*)d_in[5];
    const float* out_b = (const float*)d_in[6];
    float* out = (float*)d_out;

    __nv_bfloat16 *xhi, *xlo, *whi, *wlo, *owhi, *owlo, *ahi, *alo;
    cudaGetSymbolAddress((void**)&xhi,  g_Xhi);  cudaGetSymbolAddress((void**)&xlo,  g_Xlo);
    cudaGetSymbolAddress((void**)&whi,  g_Whi);  cudaGetSymbolAddress((void**)&wlo,  g_Wlo);
    cudaGetSymbolAddress((void**)&owhi, g_OWhi); cudaGetSymbolAddress((void**)&owlo, g_OWlo);
    cudaGetSymbolAddress((void**)&ahi,  g_Ahi);  cudaGetSymbolAddress((void**)&alo,  g_Alo);

    // 0) fp32 -> bf16 hi/lo splits
    cvt_split_kernel<<<(TB * E_DIM / 4 + 255) / 256, 256>>>(query, xhi, xlo, TB * E_DIM / 4);
    cvt_split_kernel<<<(E3 * E_DIM / 4 + 255) / 256, 256>>>(in_w, whi, wlo, E3 * E_DIM / 4);
    cvt_split_kernel<<<(E_DIM * E_DIM / 4 + 255) / 256, 256>>>(out_w, owhi, owlo, E_DIM * E_DIM / 4);

    // 1) QKV projection via HMMA (exact R13)
    hmma_gemm_kernel<0><<<dim3(E3 / 64, TB / 128), 128>>>(xhi, xlo, whi, wlo, in_b, nullptr);

    // 2) HMMA flash attention (BM=128, 8 warps, R13 per-warp stream)
    cudaFuncSetAttribute(flash_hmma_kernel,
                         cudaFuncAttributeMaxDynamicSharedMemorySize, FSMEM);
    flash_hmma_kernel<<<dim3(B_DIM * H_DIM, T_DIM / 128), 256, FSMEM>>>();

    // 3) Output projection via HMMA (exact R13)
    hmma_gemm_kernel<1><<<dim3(E_DIM / 64, TB / 128), 128>>>(ahi, alo, owhi, owlo, out_b, out);
}

// round 17
// speedup vs baseline: 1.1352x; 1.0786x over previous
#include <cuda_runtime.h>
#include <cuda_bf16.h>
#include <cstdint>

// Problem constants
#define T_DIM 2048
#define B_DIM 2
#define E_DIM 1024
#define H_DIM 16
#define DH    64
#define TB    (T_DIM * B_DIM)   // 4096
#define E3    (3 * E_DIM)       // 3072

#define LOG2E 1.4426950408889634f

// ---------------------------------------------------------------------------
// Device scratch (no runtime allocation allowed)
// ---------------------------------------------------------------------------
__device__ __nv_bfloat16 g_Qh[B_DIM * H_DIM * T_DIM * DH], g_Ql[B_DIM * H_DIM * T_DIM * DH];
__device__ __nv_bfloat16 g_Kh[B_DIM * H_DIM * T_DIM * DH], g_Kl[B_DIM * H_DIM * T_DIM * DH];
// V stored TRANSPOSED: [bh][d][t]
__device__ __nv_bfloat16 g_Vth[B_DIM * H_DIM * DH * T_DIM], g_Vtl[B_DIM * H_DIM * DH * T_DIM];

__device__ __nv_bfloat16 g_Xhi[TB * E_DIM],  g_Xlo[TB * E_DIM];        // query split
__device__ __nv_bfloat16 g_Whi[E3 * E_DIM],  g_Wlo[E3 * E_DIM];        // in_proj_weight split
__device__ __nv_bfloat16 g_OWhi[E_DIM * E_DIM], g_OWlo[E_DIM * E_DIM]; // out_w split
__device__ __nv_bfloat16 g_Ahi[TB * E_DIM],  g_Alo[TB * E_DIM];        // attn output split

// ---------------------------------------------------------------------------
// Helpers (proven)
// ---------------------------------------------------------------------------
__device__ __forceinline__ uint32_t smem_u32(const void* p) {
    uint32_t a;
    asm("{ .reg .u64 t; cvta.to.shared.u64 t, %1; cvt.u32.u64 %0, t; }" : "=r"(a) : "l"(p));
    return a;
}

__device__ __forceinline__ void ldsm_x4(uint32_t& r0, uint32_t& r1, uint32_t& r2,
                                        uint32_t& r3, uint32_t addr) {
    asm volatile("ldmatrix.sync.aligned.m8n8.x4.shared.b16 {%0,%1,%2,%3}, [%4];"
                 : "=r"(r0), "=r"(r1), "=r"(r2), "=r"(r3) : "r"(addr));
}

__device__ __forceinline__ void mma_bf16(float* d, const uint32_t* a, const uint32_t* b) {
    asm volatile(
        "mma.sync.aligned.m16n8k16.row.col.f32.bf16.bf16.f32 "
        "{%0,%1,%2,%3}, {%4,%5,%6,%7}, {%8,%9}, {%0,%1,%2,%3};"
        : "+f"(d[0]), "+f"(d[1]), "+f"(d[2]), "+f"(d[3])
        : "r"(a[0]), "r"(a[1]), "r"(a[2]), "r"(a[3]), "r"(b[0]), "r"(b[1]));
}

__device__ __forceinline__ uint32_t pack2(float a, float b) {
    __nv_bfloat162 p(__float2bfloat16(a), __float2bfloat16(b));
    return *reinterpret_cast<uint32_t*>(&p);
}
__device__ __forceinline__ uint32_t pack_hi2(float a, float b, float& ra, float& rb) {
    __nv_bfloat16 ha = __float2bfloat16(a), hb = __float2bfloat16(b);
    ra = a - __bfloat162float(ha);
    rb = b - __bfloat162float(hb);
    __nv_bfloat162 p(ha, hb);
    return *reinterpret_cast<uint32_t*>(&p);
}

// ---------------------------------------------------------------------------
// Kernel 0: fused fp32 -> (bf16 hi, bf16 lo) split for all three inputs.
// ---------------------------------------------------------------------------
#define N4_X  (TB * E_DIM / 4)        // 1048576
#define N4_W  (E3 * E_DIM / 4)        // 786432
#define N4_OW (E_DIM * E_DIM / 4)     // 262144

__global__ __launch_bounds__(256) void cvt_split_all_kernel(
    const float* __restrict__ x, const float* __restrict__ wv,
    const float* __restrict__ ow)
{
    int i = blockIdx.x * blockDim.x + threadIdx.x;
    const float* src;
    __nv_bfloat16 *hi, *lo;
    int j = i;
    if (i < N4_X)                { src = x;  hi = g_Xhi;  lo = g_Xlo; }
    else if (i < N4_X + N4_W)    { src = wv; hi = g_Whi;  lo = g_Wlo;  j = i - N4_X; }
    else if (i < N4_X + N4_W + N4_OW) { src = ow; hi = g_OWhi; lo = g_OWlo; j = i - N4_X - N4_W; }
    else return;

    float4 v = reinterpret_cast<const float4*>(src)[j];
    float r0, r1, r2, r3;
    uint32_t h01 = pack_hi2(v.x, v.y, r0, r1);
    uint32_t h23 = pack_hi2(v.z, v.w, r2, r3);
    reinterpret_cast<uint2*>(hi)[j] = make_uint2(h01, h23);
    reinterpret_cast<uint2*>(lo)[j] = make_uint2(pack2(r0, r1), pack2(r2, r3));
}

// ---------------------------------------------------------------------------
// HMMA split-bf16 GEMM — R13 structure with BK=64 (half the barriers).
// 128x64 CTA tile, 128 threads, PITCH=144 (conflict-free odd stride),
// dynamic smem 55296B, 4 CTAs/SM.
// MODE 0: QKV -> bf16 hi/lo: Q(*0.125*log2e)/K as [bh][t][dh]; V^T [bh][d][t].
// MODE 1: out-proj -> fp32 d_out.
// ---------------------------------------------------------------------------
#define BK     64
#define PITCH  144
#define ABUF   (128 * PITCH)   // 18432
#define BBUF   (64 * PITCH)    // 9216
#define GSMEM  (2 * ABUF + 2 * BBUF)  // 55296

template<int MODE>
__global__ __launch_bounds__(128, 4) void hmma_gemm_kernel(
    const __nv_bfloat16* __restrict__ Ahi, const __nv_bfloat16* __restrict__ Alo,
    const __nv_bfloat16* __restrict__ Bhi, const __nv_bfloat16* __restrict__ Blo,
    const float* __restrict__ bias, float* __restrict__ out)
{
    extern __shared__ char smem[];
    char* sAh = smem;
    char* sAl = smem + ABUF;
    char* sBh = smem + 2 * ABUF;
    char* sBl = smem + 2 * ABUF + BBUF;

    const int tid  = threadIdx.x;
    const int wid  = tid >> 5;
    const int lane = tid & 31;
    const int rowBase = blockIdx.y * 128;
    const int colBase = blockIdx.x * 64;

    const uint32_t sb_Ah = smem_u32(sAh);
    const uint32_t sb_Al = smem_u32(sAl);
    const uint32_t sb_Bh = smem_u32(sBh);
    const uint32_t sb_Bl = smem_u32(sBl);

    float acc[2][8][4];
#pragma unroll
    for (int i = 0; i < 2; i++)
#pragma unroll
        for (int j = 0; j < 8; j++)
#pragma unroll
            for (int k = 0; k < 4; k++) acc[i][j][k] = 0.0f;

    const uint32_t aoff = (uint32_t)((wid * 32 + (lane & 15)) * PITCH + (lane >> 4) * 16);
    const uint32_t boff = (uint32_t)(((lane >> 4) * 8 + (lane & 7)) * PITCH +
                                     ((lane >> 3) & 1) * 16);

    for (int k0 = 0; k0 < E_DIM; k0 += BK) {
        __syncthreads();
        // A: 128 rows x 8 segs of 16B = 1024 units (8/thread)
#pragma unroll
        for (int s = 0; s < 8; s++) {
            int unit = tid + s * 128;
            int row = unit >> 3, seg = unit & 7;
            uint32_t so = (uint32_t)(row * PITCH + seg * 16);
            size_t ao = (size_t)(rowBase + row) * E_DIM + k0 + seg * 8;
            *reinterpret_cast<uint4*>(sAh + so) = *reinterpret_cast<const uint4*>(Ahi + ao);
            *reinterpret_cast<uint4*>(sAl + so) = *reinterpret_cast<const uint4*>(Alo + ao);
        }
        // B: 64 rows x 8 segs = 512 units (4/thread)
#pragma unroll
        for (int s = 0; s < 4; s++) {
            int unit = tid + s * 128;
            int row = unit >> 3, seg = unit & 7;
            uint32_t so = (uint32_t)(row * PITCH + seg * 16);
            size_t bo = (size_t)(colBase + row) * E_DIM + k0 + seg * 8;
            *reinterpret_cast<uint4*>(sBh + so) = *reinterpret_cast<const uint4*>(Bhi + bo);
            *reinterpret_cast<uint4*>(sBl + so) = *reinterpret_cast<const uint4*>(Blo + bo);
        }
        __syncthreads();

#pragma unroll
        for (int ks = 0; ks < BK; ks += 16) {
            const uint32_t kb = (uint32_t)(ks * 2);
            uint32_t ah[2][4], al[2][4];
#pragma unroll
            for (int mt = 0; mt < 2; mt++) {
                uint32_t ar = aoff + (uint32_t)(mt * 16 * PITCH) + kb;
                ldsm_x4(ah[mt][0], ah[mt][1], ah[mt][2], ah[mt][3], sb_Ah + ar);
                ldsm_x4(al[mt][0], al[mt][1], al[mt][2], al[mt][3], sb_Al + ar);
            }
#pragma unroll
            for (int np = 0; np < 4; np++) {
                uint32_t br = boff + (uint32_t)(np * 16 * PITCH) + kb;
                uint32_t bh[4], bl[4];
                ldsm_x4(bh[0], bh[1], bh[2], bh[3], sb_Bh + br);
                ldsm_x4(bl[0], bl[1], bl[2], bl[3], sb_Bl + br);
#pragma unroll
                for (int mt = 0; mt < 2; mt++) {
#pragma unroll
                    for (int j = 0; j < 2; j++) {
                        float* d = acc[mt][np * 2 + j];
                        mma_bf16(d, ah[mt], &bh[j * 2]);
                        mma_bf16(d, ah[mt], &bl[j * 2]);
                        mma_bf16(d, al[mt], &bh[j * 2]);
                    }
                }
            }
        }
    }

    const int rloc = wid * 32 + (lane >> 2);

    if (MODE == 0) {
        const int f0 = colBase;
        const int which = f0 >> 10;
        const int h = (f0 & 1023) >> 6;
        if (which < 2) {
            __nv_bfloat16* dsth = (which == 0) ? g_Qh : g_Kh;
            __nv_bfloat16* dstl = (which == 0) ? g_Ql : g_Kl;
            // Q pre-scaled by DH^-0.5 * log2(e) so softmax can use exp2
            const float scale = (which == 0) ? (0.125f * LOG2E) : 1.0f;
#pragma unroll
            for (int mt = 0; mt < 2; mt++) {
#pragma unroll
                for (int half = 0; half < 2; half++) {
                    int r = rowBase + rloc + mt * 16 + half * 8;
                    int t = r >> 1, bb = r & 1;
                    size_t rb = ((size_t)(bb * H_DIM + h) * T_DIM + t) * DH;
#pragma unroll
                    for (int nt = 0; nt < 8; nt++) {
                        int d = nt * 8 + (lane & 3) * 2;
                        float v0 = (acc[mt][nt][half * 2 + 0] + bias[f0 + d])     * scale;
                        float v1 = (acc[mt][nt][half * 2 + 1] + bias[f0 + d + 1]) * scale;
                        float ra, rbf;
                        uint32_t hh = pack_hi2(v0, v1, ra, rbf);
                        *reinterpret_cast<uint32_t*>(&dsth[rb + d]) = hh;
                        *reinterpret_cast<uint32_t*>(&dstl[rb + d]) = pack2(ra, rbf);
                    }
                }
            }
        } else {
#pragma unroll
            for (int mt = 0; mt < 2; mt++) {
#pragma unroll
                for (int half = 0; half < 2; half++) {
                    int r = rowBase + rloc + mt * 16 + half * 8;
                    int t = r >> 1, bb = r & 1;
                    size_t cb = (size_t)(bb * H_DIM + h) * DH * T_DIM;
#pragma unroll
                    for (int nt = 0; nt < 8; nt++) {
                        int d = nt * 8 + (lane & 3) * 2;
#pragma unroll
                        for (int e = 0; e < 2; e++) {
                            float v = acc[mt][nt][half * 2 + e] + bias[f0 + d + e];
                            __nv_bfloat16 vh = __float2bfloat16(v);
                            __nv_bfloat16 vl = __float2bfloat16(v - __bfloat162float(vh));
                            size_t idx = cb + (size_t)(d + e) * T_DIM + t;
                            g_Vth[idx] = vh;
                            g_Vtl[idx] = vl;
                        }
                    }
                }
            }
        }
    } else {
#pragma unroll
        for (int mt = 0; mt < 2; mt++) {
#pragma unroll
            for (int half = 0; half < 2; half++) {
                int r = rowBase + rloc + mt * 16 + half * 8;
                float* dst = out + (size_t)r * E_DIM;
#pragma unroll
                for (int nt = 0; nt < 8; nt++) {
                    int c = colBase + nt * 8 + (lane & 3) * 2;
                    float2 v;
                    v.x = acc[mt][nt][half * 2 + 0] + bias[c];
                    v.y = acc[mt][nt][half * 2 + 1] + bias[c + 1];
                    *reinterpret_cast<float2*>(dst + c) = v;
                }
            }
        }
    }
}

// ---------------------------------------------------------------------------
// Kernel 2: HMMA flash attention — EXACT R13 (passing) kernel; only change:
// exp2f instead of __expf (Q was pre-scaled by log2e in the QKV epilogue).
// ---------------------------------------------------------------------------
#define FPITCH 72
#define FPB    (FPITCH * 2)          // 144 bytes/row
#define FBUF   (64 * FPB)            // 9216 bytes
#define FSMEM  (6 * FBUF)            // 55296 bytes

__global__ __launch_bounds__(128) void flash_hmma_kernel()
{
    extern __shared__ char fsm[];
    char* sQh = fsm;
    char* sKh = fsm + 2 * FBUF;
    char* sKl = fsm + 3 * FBUF;
    char* sVt = fsm + 4 * FBUF;
    char* sVl = fsm + 5 * FBUF;

    const int tid = threadIdx.x;
    const int lane = tid & 31;
    const int w = tid >> 5;
    const int bh = blockIdx.x;
    const int q0 = blockIdx.y * 64;

    const size_t hbase = (size_t)bh * T_DIM * DH;
    const __nv_bfloat16* Qhg = g_Qh + hbase;
    const __nv_bfloat16* Qlg = g_Ql + hbase;
    const __nv_bfloat16* Khg = g_Kh + hbase;
    const __nv_bfloat16* Klg = g_Kl + hbase;
    const __nv_bfloat16* Vthg = g_Vth + (size_t)bh * DH * T_DIM;
    const __nv_bfloat16* Vtlg = g_Vtl + (size_t)bh * DH * T_DIM;

    // Stage Q tile (hi/lo): pure copies
#pragma unroll
    for (int s = 0; s < 4; s++) {
        int unit = tid + s * 128;
        int row = unit >> 3, seg = unit & 7;
        int go = (q0 + row) * DH + seg * 8;
        uint32_t so = (uint32_t)(row * FPB + seg * 16);
        *reinterpret_cast<uint4*>(sQh + so)        = *reinterpret_cast<const uint4*>(Qhg + go);
        *reinterpret_cast<uint4*>(sQh + FBUF + so) = *reinterpret_cast<const uint4*>(Qlg + go);
    }
    __syncthreads();

    // Persistent Q A-fragments
    uint32_t aqh[4][4], aql[4][4];
    const uint32_t qaddr = smem_u32(sQh) +
        (uint32_t)((w * 16 + (lane & 15)) * FPB + (lane >> 4) * 16);
#pragma unroll
    for (int ks = 0; ks < 4; ks++) {
        ldsm_x4(aqh[ks][0], aqh[ks][1], aqh[ks][2], aqh[ks][3], qaddr + ks * 32);
        ldsm_x4(aql[ks][0], aql[ks][1], aql[ks][2], aql[ks][3], qaddr + FBUF + ks * 32);
    }

    float o[8][4];
#pragma unroll
    for (int i = 0; i < 8; i++)
#pragma unroll
        for (int j = 0; j < 4; j++) o[i][j] = 0.0f;
    float m1 = -1e30f, m2 = -1e30f, l1 = 0.0f, l2 = 0.0f;

    const uint32_t blanes = (uint32_t)(((lane >> 4) * 8 + (lane & 7)) * FPB +
                                       ((lane >> 3) & 1) * 16);
    const uint32_t kaddr = smem_u32(sKh) + blanes;
    const uint32_t vaddr = smem_u32(sVt) + blanes;

    for (int kt = 0; kt < T_DIM; kt += 64) {
        __syncthreads();
#pragma unroll
        for (int s = 0; s < 4; s++) {
            int unit = tid + s * 128;
            int row = unit >> 3, seg = unit & 7;
            uint32_t so = (uint32_t)(row * FPB + seg * 16);
            int gk = (kt + row) * DH + seg * 8;
            int gv = row * T_DIM + kt + seg * 8;
            *reinterpret_cast<uint4*>(sKh + so) = *reinterpret_cast<const uint4*>(Khg + gk);
            *reinterpret_cast<uint4*>(sKl + so) = *reinterpret_cast<const uint4*>(Klg + gk);
            *reinterpret_cast<uint4*>(sVt + so) = *reinterpret_cast<const uint4*>(Vthg + gv);
            *reinterpret_cast<uint4*>(sVl + so) = *reinterpret_cast<const uint4*>(Vtlg + gv);
        }
        __syncthreads();

        // S' = (Q*log2e/8) K^T  — scores in base-2 domain
        float s4[8][4];
#pragma unroll
        for (int i = 0; i < 8; i++)
#pragma unroll
            for (int j = 0; j < 4; j++) s4[i][j] = 0.0f;

#pragma unroll
        for (int ks = 0; ks < 4; ks++) {
#pragma unroll
            for (int np = 0; np < 4; np++) {
                uint32_t ba = kaddr + (uint32_t)(np * 16 * FPB) + ks * 32;
                uint32_t bhf[4], blf[4];
                ldsm_x4(bhf[0], bhf[1], bhf[2], bhf[3], ba);
                ldsm_x4(blf[0], blf[1], blf[2], blf[3], ba + FBUF);
#pragma unroll
                for (int j = 0; j < 2; j++) {
                    float* d = s4[np * 2 + j];
                    mma_bf16(d, aqh[ks], &bhf[j * 2]);
                    mma_bf16(d, aqh[ks], &blf[j * 2]);
                    mma_bf16(d, aql[ks], &bhf[j * 2]);
                }
            }
        }

        // Online softmax (base-2)
        float mx1 = -1e30f, mx2 = -1e30f;
#pragma unroll
        for (int nt = 0; nt < 8; nt++) {
            mx1 = fmaxf(mx1, fmaxf(s4[nt][0], s4[nt][1]));
            mx2 = fmaxf(mx2, fmaxf(s4[nt][2], s4[nt][3]));
        }
        mx1 = fmaxf(mx1, __shfl_xor_sync(0xffffffffu, mx1, 1));
        mx1 = fmaxf(mx1, __shfl_xor_sync(0xffffffffu, mx1, 2));
        mx2 = fmaxf(mx2, __shfl_xor_sync(0xffffffffu, mx2, 1));
        mx2 = fmaxf(mx2, __shfl_xor_sync(0xffffffffu, mx2, 2));

        float mn1 = fmaxf(m1, mx1), mn2 = fmaxf(m2, mx2);
        float c1 = exp2f(m1 - mn1), c2 = exp2f(m2 - mn2);
        m1 = mn1; m2 = mn2;

        float p1 = 0.0f, p2 = 0.0f;
#pragma unroll
        for (int nt = 0; nt < 8; nt++) {
            s4[nt][0] = exp2f(s4[nt][0] - mn1); p1 += s4[nt][0];
            s4[nt][1] = exp2f(s4[nt][1] - mn1); p1 += s4[nt][1];
            s4[nt][2] = exp2f(s4[nt][2] - mn2); p2 += s4[nt][2];
            s4[nt][3] = exp2f(s4[nt][3] - mn2); p2 += s4[nt][3];
        }
        l1 = l1 * c1 + p1;
        l2 = l2 * c2 + p2;
#pragma unroll
        for (int nt = 0; nt < 8; nt++) {
            o[nt][0] *= c1; o[nt][1] *= c1;
            o[nt][2] *= c2; o[nt][3] *= c2;
        }

        // Pack P as A-fragments (C->A identity), hi/lo
        uint32_t ph[4][4], pl[4][4];
#pragma unroll
        for (int ks = 0; ks < 4; ks++) {
            float ra, rb;
            ph[ks][0] = pack_hi2(s4[2 * ks][0],     s4[2 * ks][1],     ra, rb);
            pl[ks][0] = pack2(ra, rb);
            ph[ks][1] = pack_hi2(s4[2 * ks][2],     s4[2 * ks][3],     ra, rb);
            pl[ks][1] = pack2(ra, rb);
            ph[ks][2] = pack_hi2(s4[2 * ks + 1][0], s4[2 * ks + 1][1], ra, rb);
            pl[ks][2] = pack2(ra, rb);
            ph[ks][3] = pack_hi2(s4[2 * ks + 1][2], s4[2 * ks + 1][3], ra, rb);
            pl[ks][3] = pack2(ra, rb);
        }

        // O += P V
#pragma unroll
        for (int ks = 0; ks < 4; ks++) {
#pragma unroll
            for (int np = 0; np < 4; np++) {
                uint32_t ba = vaddr + (uint32_t)(np * 16 * FPB) + ks * 32;
                uint32_t bvh[4], bvl[4];
                ldsm_x4(bvh[0], bvh[1], bvh[2], bvh[3], ba);
                ldsm_x4(bvl[0], bvl[1], bvl[2], bvl[3], ba + FBUF);
#pragma unroll
                for (int j = 0; j < 2; j++) {
                    float* d = o[np * 2 + j];
                    mma_bf16(d, ph[ks], &bvh[j * 2]);
                    mma_bf16(d, ph[ks], &bvl[j * 2]);
                    mma_bf16(d, pl[ks], &bvh[j * 2]);
                }
            }
        }
    }

    // Epilogue
    l1 += __shfl_xor_sync(0xffffffffu, l1, 1);
    l1 += __shfl_xor_sync(0xffffffffu, l1, 2);
    l2 += __shfl_xor_sync(0xffffffffu, l2, 1);
    l2 += __shfl_xor_sync(0xffffffffu, l2, 2);
    const float inv1 = 1.0f / l1, inv2 = 1.0f / l2;

    const int r1 = q0 + w * 16 + (lane >> 2);
    const int r2 = r1 + 8;
    const int b = bh >> 4;
    const int h = bh & 15;

#pragma unroll
    for (int nt = 0; nt < 8; nt++) {
        int d = nt * 8 + (lane & 3) * 2;
        float ra, rb;
        uint32_t hh = pack_hi2(o[nt][0] * inv1, o[nt][1] * inv1, ra, rb);
        size_t i1 = ((size_t)r1 * B_DIM + b) * E_DIM + h * DH + d;
        *reinterpret_cast<uint32_t*>(&g_Ahi[i1]) = hh;
        *reinterpret_cast<uint32_t*>(&g_Alo[i1]) = pack2(ra, rb);
        hh = pack_hi2(o[nt][2] * inv2, o[nt][3] * inv2, ra, rb);
        size_t i2 = ((size_t)r2 * B_DIM + b) * E_DIM + h * DH + d;
        *reinterpret_cast<uint32_t*>(&g_Ahi[i2]) = hh;
        *reinterpret_cast<uint32_t*>(&g_Alo[i2]) = pack2(ra, rb);
    }
}

// ---------------------------------------------------------------------------
// Launch
// ---------------------------------------------------------------------------
extern "C" void kernel_launch(void* const* d_in, const int* in_sizes, int n_in,
                              void* d_out, int out_size)
{
    const float* query = (const float*)d_in[0];
    const float* in_w  = (const float*)d_in[3];
    const float* in_b  = (const float*)d_in[4];
    const float* out_w = (const float*)d_in[5];
    const float* out_b = (const float*)d_in[6];
    float* out = (float*)d_out;

    __nv_bfloat16 *xhi, *xlo, *whi, *wlo, *owhi, *owlo, *ahi, *alo;
    cudaGetSymbolAddress((void**)&xhi,  g_Xhi);  cudaGetSymbolAddress((void**)&xlo,  g_Xlo);
    cudaGetSymbolAddress((void**)&whi,  g_Whi);  cudaGetSymbolAddress((void**)&wlo,  g_Wlo);
    cudaGetSymbolAddress((void**)&owhi, g_OWhi); cudaGetSymbolAddress((void**)&owlo, g_OWlo);
    cudaGetSymbolAddress((void**)&ahi,  g_Ahi);  cudaGetSymbolAddress((void**)&alo,  g_Alo);

    // 0) fused fp32 -> bf16 hi/lo splits (one launch)
    const int n4_total = N4_X + N4_W + N4_OW;
    cvt_split_all_kernel<<<(n4_total + 255) / 256, 256>>>(query, in_w, out_w);

    // 1) QKV projection via HMMA (BK=64)
    cudaFuncSetAttribute(hmma_gemm_kernel<0>,
                         cudaFuncAttributeMaxDynamicSharedMemorySize, GSMEM);
    hmma_gemm_kernel<0><<<dim3(E3 / 64, TB / 128), 128, GSMEM>>>(
        xhi, xlo, whi, wlo, in_b, nullptr);

    // 2) HMMA flash attention (R13 + exp2)
    cudaFuncSetAttribute(flash_hmma_kernel,
                         cudaFuncAttributeMaxDynamicSharedMemorySize, FSMEM);
    flash_hmma_kernel<<<dim3(B_DIM * H_DIM, T_DIM / 64), 128, FSMEM>>>();

    // 3) Output projection via HMMA (BK=64)
    cudaFuncSetAttribute(hmma_gemm_kernel<1>,
                         cudaFuncAttributeMaxDynamicSharedMemorySize, GSMEM);
    hmma_gemm_kernel<1><<<dim3(E_DIM / 64, TB / 128), 128, GSMEM>>>(
        ahi, alo, owhi, owlo, out_b, out);
}